// round 10
// baseline (speedup 1.0000x reference)
#include <cuda_runtime.h>
#include <cuda_fp16.h>
#include <cstdint>

#define D_DIM 512
#define C_DIM 512
#define K3    1536
#define MAXN  100000
#define MAXE  100000

// ------------------------------ scratch ------------------------------------
__device__ __half g_Mh[(size_t)MAXN * K3];   // [Nc][1536] fp16 (compacted rows)
__device__ __half g_Bh[C_DIM * K3];          // [c][k] row-major fp16
__device__ int g_cnt[MAXN];                  // in-degree (re-zeroed each run)
__device__ int g_off[MAXN + 1];
__device__ int g_cur[MAXN];
__device__ int g_eidx[MAXE];
__device__ int g_cid[MAXN];                  // prefix count of nonzero rows before n (ALL n)
__device__ int g_orig[MAXN];                 // compact row -> node
__device__ int g_Nc;                         // number of non-empty rows

// ------------------------------ helpers ------------------------------------
__device__ __forceinline__ uint32_t smem_to_u32(const void* smem_ptr) {
    uint32_t addr;
    asm("{ .reg .u64 tmp; cvta.to.shared.u64 tmp, %1; cvt.u32.u64 %0, tmp; }"
        : "=r"(addr) : "l"(smem_ptr));
    return addr;
}

__device__ __forceinline__ void cp_async16(uint32_t dst, const void* src, uint32_t src_bytes) {
    asm volatile("cp.async.cg.shared.global [%0], [%1], 16, %2;"
                 :: "r"(dst), "l"(src), "r"(src_bytes));
}
__device__ __forceinline__ void cp_commit() {
    asm volatile("cp.async.commit_group;" ::: "memory");
}
__device__ __forceinline__ void cp_wait1() {
    asm volatile("cp.async.wait_group 1;" ::: "memory");
}
__device__ __forceinline__ void cp_wait0() {
    asm volatile("cp.async.wait_group 0;" ::: "memory");
}

__device__ __forceinline__ void ldsm_x4(uint32_t* r, uint32_t addr) {
    asm volatile("ldmatrix.sync.aligned.m8n8.x4.shared.b16 {%0,%1,%2,%3}, [%4];"
                 : "=r"(r[0]), "=r"(r[1]), "=r"(r[2]), "=r"(r[3]) : "r"(addr));
}

__device__ __forceinline__ void mma16816(float* d, const uint32_t* a, uint32_t b0, uint32_t b1) {
    asm volatile("mma.sync.aligned.m16n8k16.row.col.f32.f16.f16.f32 "
                 "{%0,%1,%2,%3}, {%4,%5,%6,%7}, {%8,%9}, {%0,%1,%2,%3};"
                 : "+f"(d[0]), "+f"(d[1]), "+f"(d[2]), "+f"(d[3])
                 : "r"(a[0]), "r"(a[1]), "r"(a[2]), "r"(a[3]), "r"(b0), "r"(b1));
}

__device__ __forceinline__ float tanh_fast(float x) {
    float y;
    asm("tanh.approx.f32 %0, %1;" : "=f"(y) : "f"(x));
    return y;
}

// ------------------------------ CSR build ----------------------------------
__global__ void hist_kernel(const int* __restrict__ dst, int E) {
    int e = blockIdx.x * blockDim.x + threadIdx.x;
    if (e < E) atomicAdd(&g_cnt[dst[e]], 1);
}

// scan: edge offsets + nonzero-row prefix (g_cid for ALL nodes) + compaction
__global__ void scan_kernel(int N) {
    __shared__ int shA[1024];
    __shared__ int shB[1024];
    int t = threadIdx.x;
    int chunk = (N + 1023) >> 10;
    int s0 = t * chunk;
    int s1 = s0 + chunk; if (s1 > N) s1 = N;
    int sum = 0, nz = 0;
    for (int i = s0; i < s1; i++) {
        int c = g_cnt[i];
        sum += c;
        nz += (c > 0);
    }
    shA[t] = sum;
    shB[t] = nz;
    __syncthreads();
    for (int off = 1; off < 1024; off <<= 1) {
        int va = shA[t], vb = shB[t];
        int oa = (t >= off) ? shA[t - off] : 0;
        int ob = (t >= off) ? shB[t - off] : 0;
        __syncthreads();
        shA[t] = va + oa;
        shB[t] = vb + ob;
        __syncthreads();
    }
    int runA = shA[t] - sum;
    int runB = shB[t] - nz;
    for (int i = s0; i < s1; i++) {
        int c = g_cnt[i];
        g_off[i] = runA;
        g_cur[i] = runA;
        runA += c;
        g_cid[i] = runB;               // exclusive prefix, ALL nodes
        if (c > 0) {
            g_orig[runB] = i;
            runB++;
        }
    }
    if (t == 0) g_off[N] = shA[1023];
    if (t == 1023) g_Nc = shB[1023];
}

// fill edge lists; ALSO re-zero g_cnt for the next graph replay
__global__ void fill_kernel(const int* __restrict__ dst, int E, int N) {
    int e = blockIdx.x * blockDim.x + threadIdx.x;
    if (e < E) {
        int p = atomicAdd(&g_cur[dst[e]], 1);
        g_eidx[p] = e;
    }
    if (e < N) g_cnt[e] = 0;
}

// ------- warp-per-node gather-reduce (node range) ; zerofill fused ---------
__global__ void reduce_kernel(const float* __restrict__ x,
                              const float* __restrict__ eta,
                              const int* __restrict__ src,
                              const float* __restrict__ bias,
                              float* __restrict__ out,
                              int nLo, int nHi) {
    int n = nLo + ((blockIdx.x * blockDim.x + threadIdx.x) >> 5);
    if (n >= nHi) return;
    int lane = threadIdx.x & 31;
    int beg = g_off[n], end = g_off[n + 1];

    if (beg == end) {
        #pragma unroll
        for (int q = 0; q < 4; q++) {
            float4 b = __ldg((const float4*)bias + q * 32 + lane);
            b.x = tanh_fast(b.x); b.y = tanh_fast(b.y);
            b.z = tanh_fast(b.z); b.w = tanh_fast(b.w);
            ((float4*)(out + (size_t)n * C_DIM))[q * 32 + lane] = b;
        }
        return;
    }

    float4 a0[4], a1[4], a2[4];
    #pragma unroll
    for (int q = 0; q < 4; q++) {
        a0[q] = make_float4(0.f, 0.f, 0.f, 0.f);
        a1[q] = a0[q];
        a2[q] = a0[q];
    }
    for (int j = beg; j < end; j++) {
        int e = g_eidx[j];
        int s = __ldg(src + e);
        float e0 = __ldg(eta + e * 3 + 0);
        float e1 = __ldg(eta + e * 3 + 1);
        float e2 = __ldg(eta + e * 3 + 2);
        const float4* xr = (const float4*)x + (size_t)s * 128;
        #pragma unroll
        for (int q = 0; q < 4; q++) {
            float4 xv = __ldg(xr + q * 32 + lane);
            a0[q].x += e0 * xv.x; a0[q].y += e0 * xv.y; a0[q].z += e0 * xv.z; a0[q].w += e0 * xv.w;
            a1[q].x += e1 * xv.x; a1[q].y += e1 * xv.y; a1[q].z += e1 * xv.z; a1[q].w += e1 * xv.w;
            a2[q].x += e2 * xv.x; a2[q].y += e2 * xv.y; a2[q].z += e2 * xv.z; a2[q].w += e2 * xv.w;
        }
    }
    size_t base = (size_t)g_cid[n] * K3;
    #pragma unroll
    for (int q = 0; q < 4; q++) {
        __half h0[4] = {__float2half(a0[q].x), __float2half(a0[q].y),
                        __float2half(a0[q].z), __float2half(a0[q].w)};
        __half h1[4] = {__float2half(a1[q].x), __float2half(a1[q].y),
                        __float2half(a1[q].z), __float2half(a1[q].w)};
        __half h2[4] = {__float2half(a2[q].x), __float2half(a2[q].y),
                        __float2half(a2[q].z), __float2half(a2[q].w)};
        int o = (q * 32 + lane) * 4;
        *(uint2*)(g_Mh + base + 0 * 512 + o) = *(uint2*)h0;
        *(uint2*)(g_Mh + base + 1 * 512 + o) = *(uint2*)h1;
        *(uint2*)(g_Mh + base + 2 * 512 + o) = *(uint2*)h2;
    }
}

// ---------------- prepW: tiled transpose, coalesced both sides -------------
__global__ void prepW_kernel(const float* __restrict__ W) {
    __shared__ float tile[32][33];
    int s  = blockIdx.z;
    int c0 = blockIdx.x * 32;
    int d0 = blockIdx.y * 32;
    int tx = threadIdx.x;
    int ty = threadIdx.y;
    #pragma unroll
    for (int q = 0; q < 4; q++) {
        int d = d0 + ty + q * 8;
        tile[ty + q * 8][tx] = W[(size_t)d * K3 + s * C_DIM + c0 + tx];
    }
    __syncthreads();
    #pragma unroll
    for (int q = 0; q < 4; q++) {
        int c = c0 + ty + q * 8;
        g_Bh[(size_t)c * K3 + s * D_DIM + d0 + tx] = __float2half(tile[tx][ty + q * 8]);
    }
}

// ------------------------------- GEMM (chunked) ----------------------------
// chunk processes m-tiles [done_prev, done_cur), bounds from g_cid prefix.
#define TM 128
#define TN 256
#define TK 64
#define ROWB 144
#define MAT_A (128 * ROWB)
#define MAT_B (256 * ROWB)
#define STAGE_BYTES (MAT_A + MAT_B)
#define NSTAGE 3
#define GEMM_SMEM (NSTAGE * STAGE_BYTES)

__global__ __launch_bounds__(512, 1)
void gemm_kernel(const float* __restrict__ bias, float* __restrict__ out,
                 int nbLo, int nbHi, int isFirst, int isLast) {
    const int Nc = g_Nc;
    // tiles fully reduced after this chunk's reduce completes
    int Rc = isLast ? Nc : g_cid[nbHi];
    int done_c = isLast ? ((Rc + 127) >> 7) : (Rc >> 7);
    int done_p = isFirst ? 0 : (g_cid[nbLo] >> 7);
    int t = done_p + (int)(blockIdx.x >> 1);
    if (t >= done_c) return;
    const int m0 = t * TM;

    extern __shared__ char dsm[];
    const uint32_t sbase = smem_to_u32(dsm);

    const int tid  = threadIdx.x;
    const int lane = tid & 31;
    const int wid  = tid >> 5;
    const int wm   = wid & 3;          // 0..3 -> 32 rows each
    const int wn   = wid >> 2;         // 0..3 -> 64 cols each

    const int nt = blockIdx.x & 1;
    const int n0 = nt * TN;

    // ---- hoisted per-thread source pointers (2 A rows, 4 B rows) ----
    const char* aSrc[2];
    uint32_t    aOk[2];
    #pragma unroll
    for (int i = 0; i < 2; i++) {
        int idx = tid + i * 512;
        int row = idx >> 3;
        int ch  = idx & 7;
        int gr = m0 + row;
        aOk[i]  = (gr < Nc) ? 16u : 0u;
        aSrc[i] = (gr < Nc) ? (const char*)(g_Mh + (size_t)gr * K3) + ch * 16
                            : (const char*)g_Mh;
    }
    const char* bSrc[4];
    #pragma unroll
    for (int i = 0; i < 4; i++) {
        int idx = tid + i * 512;
        int row = idx >> 3;
        int ch  = idx & 7;
        int br = n0 + row;
        bSrc[i] = (const char*)(g_Bh + (size_t)br * K3) + ch * 16;
    }

    auto stage_off = [&](int s) { return sbase + (uint32_t)s * STAGE_BYTES; };

    auto load_stage = [&](int s, int kc) {
        uint32_t so = stage_off(s);
        int kbyte = kc * TK * 2;
        #pragma unroll
        for (int i = 0; i < 2; i++) {
            int idx = tid + i * 512;
            int row = idx >> 3;
            int ch  = idx & 7;
            uint32_t d = (uint32_t)(row * ROWB + ch * 16);
            cp_async16(so + d, aSrc[i] + kbyte, aOk[i]);
        }
        #pragma unroll
        for (int i = 0; i < 4; i++) {
            int idx = tid + i * 512;
            int row = idx >> 3;
            int ch  = idx & 7;
            uint32_t d = (uint32_t)(row * ROWB + ch * 16);
            cp_async16(so + MAT_A + d, bSrc[i] + kbyte, 16u);
        }
    };

    float acc[2][8][4];
    #pragma unroll
    for (int i = 0; i < 2; i++)
        #pragma unroll
        for (int j = 0; j < 8; j++)
            #pragma unroll
            for (int q = 0; q < 4; q++) acc[i][j][q] = 0.f;

    const uint32_t aRow = (uint32_t)(wm * 32 + (lane & 15));
    const uint32_t bRow = (uint32_t)(wn * 64 + (lane & 15));
    const uint32_t colB = (uint32_t)((lane >> 4) * 16);

    load_stage(0, 0);
    cp_commit();
    load_stage(1, 1);
    cp_commit();

    uint32_t a[2][2][4], bh[2][4][4];

    const int NKC = K3 / TK;   // 24
    int sidx = 0;
    for (int kc = 0; kc < NKC; kc++) {
        if (kc + 1 < NKC) cp_wait1(); else cp_wait0();
        __syncthreads();
        if (kc + 2 < NKC) {
            int s2 = sidx + 2; if (s2 >= NSTAGE) s2 -= NSTAGE;
            load_stage(s2, kc + 2);
            cp_commit();
        }

        uint32_t so = stage_off(sidx);
        uint32_t aB   = so + aRow * ROWB + colB;
        uint32_t bHiB = so + MAT_A + bRow * ROWB + colB;

        #pragma unroll
        for (int i = 0; i < 2; i++)
            ldsm_x4(a[0][i], aB + (uint32_t)(i * 16) * ROWB);
        #pragma unroll
        for (int g = 0; g < 4; g++)
            ldsm_x4(bh[0][g], bHiB + (uint32_t)(g * 16) * ROWB);

        #pragma unroll
        for (int k16 = 0; k16 < 4; k16++) {
            int cur = k16 & 1;
            int nxt = cur ^ 1;
            if (k16 < 3) {
                uint32_t kb = (uint32_t)((k16 + 1) * 32);
                #pragma unroll
                for (int i = 0; i < 2; i++)
                    ldsm_x4(a[nxt][i], aB + (uint32_t)(i * 16) * ROWB + kb);
                #pragma unroll
                for (int g = 0; g < 4; g++)
                    ldsm_x4(bh[nxt][g], bHiB + (uint32_t)(g * 16) * ROWB + kb);
            }
            #pragma unroll
            for (int g = 0; g < 4; g++)
                #pragma unroll
                for (int i = 0; i < 2; i++) {
                    mma16816(acc[i][2*g],   a[cur][i], bh[cur][g][0], bh[cur][g][2]);
                    mma16816(acc[i][2*g+1], a[cur][i], bh[cur][g][1], bh[cur][g][3]);
                }
        }
        sidx++; if (sidx >= NSTAGE) sidx = 0;
    }

    // ---------------- epilogue: bias + tanh, scatter via g_orig ------------
    int orow[2][2];
    #pragma unroll
    for (int i = 0; i < 2; i++) {
        int r0 = m0 + wm * 32 + i * 16 + (lane >> 2);
        int r1 = r0 + 8;
        orow[i][0] = (r0 < Nc) ? __ldg(g_orig + r0) : -1;
        orow[i][1] = (r1 < Nc) ? __ldg(g_orig + r1) : -1;
    }
    #pragma unroll
    for (int j = 0; j < 8; j++) {
        int col = n0 + wn * 64 + j * 8 + (lane & 3) * 2;
        float b0 = __ldg(bias + col);
        float b1 = __ldg(bias + col + 1);
        #pragma unroll
        for (int i = 0; i < 2; i++) {
            if (orow[i][0] >= 0) {
                float2 o;
                o.x = tanh_fast(acc[i][j][0] + b0);
                o.y = tanh_fast(acc[i][j][1] + b1);
                *(float2*)(out + (size_t)orow[i][0] * C_DIM + col) = o;
            }
            if (orow[i][1] >= 0) {
                float2 o;
                o.x = tanh_fast(acc[i][j][2] + b0);
                o.y = tanh_fast(acc[i][j][3] + b1);
                *(float2*)(out + (size_t)orow[i][1] * C_DIM + col) = o;
            }
        }
    }
}

// ------------------------------ launch -------------------------------------
#define NCHUNK 4

extern "C" void kernel_launch(void* const* d_in, const int* in_sizes, int n_in,
                              void* d_out, int out_size) {
    const float* x    = (const float*)d_in[0];
    const float* W    = (const float*)d_in[1];
    const float* bias = (const float*)d_in[2];
    const float* eta  = (const float*)d_in[3];
    const int*   src  = (const int*)d_in[4];
    const int*   dst  = (const int*)d_in[5];
    float* out = (float*)d_out;

    int N = in_sizes[0] / D_DIM;
    int E = in_sizes[4];

    // one-time stream/event setup (first call is NOT captured)
    static cudaStream_t s1 = nullptr;
    static cudaEvent_t evStart, evEnd, evR[NCHUNK];
    static bool inited = false;
    if (!inited) {
        cudaStreamCreateWithFlags(&s1, cudaStreamNonBlocking);
        cudaEventCreateWithFlags(&evStart, cudaEventDisableTiming);
        cudaEventCreateWithFlags(&evEnd, cudaEventDisableTiming);
        for (int c = 0; c < NCHUNK; c++)
            cudaEventCreateWithFlags(&evR[c], cudaEventDisableTiming);
        cudaFuncSetAttribute(gemm_kernel,
                             cudaFuncAttributeMaxDynamicSharedMemorySize,
                             GEMM_SMEM);
        inited = true;
    }

    int CH = (N + NCHUNK - 1) / NCHUNK;
    int maxEN = (E > N) ? E : N;
    int totTiles = (N + TM - 1) / TM + 1;

    // fork s1 from the (captured) default stream
    cudaEventRecord(evStart, 0);
    cudaStreamWaitEvent(s1, evStart, 0);

    // s1: B transpose (independent of CSR chain)
    dim3 tgrid(C_DIM / 32, D_DIM / 32, 3);
    prepW_kernel<<<tgrid, dim3(32, 8), 0, s1>>>(W);

    // s0 (default): CSR build
    hist_kernel<<<(E + 255) / 256, 256>>>(dst, E);
    scan_kernel<<<1, 1024>>>(N);
    fill_kernel<<<(maxEN + 255) / 256, 256>>>(dst, E, N);

    // pipeline: reduce chunk c on s0 -> event -> gemm chunk c on s1
    for (int c = 0; c < NCHUNK; c++) {
        int nLo = c * CH; if (nLo > N) nLo = N;
        int nHi = (c + 1) * CH; if (nHi > N) nHi = N;
        int cnt = nHi - nLo;
        if (cnt > 0)
            reduce_kernel<<<(cnt * 32 + 255) / 256, 256>>>(x, eta, src, bias, out, nLo, nHi);
        cudaEventRecord(evR[c], 0);
        cudaStreamWaitEvent(s1, evR[c], 0);
        gemm_kernel<<<totTiles * 2, 512, GEMM_SMEM, s1>>>(
            bias, out, nLo, nHi, (c == 0) ? 1 : 0, (c == NCHUNK - 1) ? 1 : 0);
    }

    // join s1 back into the default stream
    cudaEventRecord(evEnd, s1);
    cudaStreamWaitEvent(0, evEnd, 0);
}

// round 11
// speedup vs baseline: 1.0005x; 1.0005x over previous
#include <cuda_runtime.h>
#include <cuda_fp16.h>
#include <cstdint>

#define D_DIM 512
#define C_DIM 512
#define K3    1536
#define MAXN  100000
#define MAXE  100000

// ------------------------------ scratch ------------------------------------
__device__ __half g_Mh[(size_t)MAXN * K3];   // [Nc][1536] fp16 (compacted rows)
__device__ __half g_Bh[C_DIM * K3];          // [c][k] row-major fp16
__device__ int g_cnt[MAXN];                  // in-degree (re-zeroed each run)
__device__ int g_off[MAXN + 1];
__device__ int g_cur[MAXN];
__device__ int g_eidx[MAXE];
__device__ int g_cid[MAXN];                  // exclusive prefix of nonzero rows
__device__ int g_orig[MAXN];                 // compact row -> node
__device__ int g_Nc;                         // number of non-empty rows

// ------------------------------ helpers ------------------------------------
__device__ __forceinline__ uint32_t smem_to_u32(const void* smem_ptr) {
    uint32_t addr;
    asm("{ .reg .u64 tmp; cvta.to.shared.u64 tmp, %1; cvt.u32.u64 %0, tmp; }"
        : "=r"(addr) : "l"(smem_ptr));
    return addr;
}

__device__ __forceinline__ void cp_async16(uint32_t dst, const void* src, uint32_t src_bytes) {
    asm volatile("cp.async.cg.shared.global [%0], [%1], 16, %2;"
                 :: "r"(dst), "l"(src), "r"(src_bytes));
}
__device__ __forceinline__ void cp_commit() {
    asm volatile("cp.async.commit_group;" ::: "memory");
}
__device__ __forceinline__ void cp_wait1() {
    asm volatile("cp.async.wait_group 1;" ::: "memory");
}
__device__ __forceinline__ void cp_wait0() {
    asm volatile("cp.async.wait_group 0;" ::: "memory");
}

__device__ __forceinline__ void ldsm_x4(uint32_t* r, uint32_t addr) {
    asm volatile("ldmatrix.sync.aligned.m8n8.x4.shared.b16 {%0,%1,%2,%3}, [%4];"
                 : "=r"(r[0]), "=r"(r[1]), "=r"(r[2]), "=r"(r[3]) : "r"(addr));
}

__device__ __forceinline__ void mma16816(float* d, const uint32_t* a, uint32_t b0, uint32_t b1) {
    asm volatile("mma.sync.aligned.m16n8k16.row.col.f32.f16.f16.f32 "
                 "{%0,%1,%2,%3}, {%4,%5,%6,%7}, {%8,%9}, {%0,%1,%2,%3};"
                 : "+f"(d[0]), "+f"(d[1]), "+f"(d[2]), "+f"(d[3])
                 : "r"(a[0]), "r"(a[1]), "r"(a[2]), "r"(a[3]), "r"(b0), "r"(b1));
}

__device__ __forceinline__ float tanh_fast(float x) {
    float y;
    asm("tanh.approx.f32 %0, %1;" : "=f"(y) : "f"(x));
    return y;
}

// ------------------------------ CSR build ----------------------------------
__global__ void hist_kernel(const int* __restrict__ dst, int E) {
    int e = blockIdx.x * blockDim.x + threadIdx.x;
    if (e < E) atomicAdd(&g_cnt[dst[e]], 1);
}

// scan: edge offsets + nonzero-row prefix + compaction
__global__ void scan_kernel(int N) {
    __shared__ int shA[1024];
    __shared__ int shB[1024];
    int t = threadIdx.x;
    int chunk = (N + 1023) >> 10;
    int s0 = t * chunk;
    int s1 = s0 + chunk; if (s1 > N) s1 = N;
    int sum = 0, nz = 0;
    for (int i = s0; i < s1; i++) {
        int c = g_cnt[i];
        sum += c;
        nz += (c > 0);
    }
    shA[t] = sum;
    shB[t] = nz;
    __syncthreads();
    for (int off = 1; off < 1024; off <<= 1) {
        int va = shA[t], vb = shB[t];
        int oa = (t >= off) ? shA[t - off] : 0;
        int ob = (t >= off) ? shB[t - off] : 0;
        __syncthreads();
        shA[t] = va + oa;
        shB[t] = vb + ob;
        __syncthreads();
    }
    int runA = shA[t] - sum;
    int runB = shB[t] - nz;
    for (int i = s0; i < s1; i++) {
        int c = g_cnt[i];
        g_off[i] = runA;
        g_cur[i] = runA;
        runA += c;
        g_cid[i] = runB;
        if (c > 0) {
            g_orig[runB] = i;
            runB++;
        }
    }
    if (t == 0) g_off[N] = shA[1023];
    if (t == 1023) g_Nc = shB[1023];
}

// fill edge lists; ALSO re-zero g_cnt for the next graph replay
__global__ void fill_kernel(const int* __restrict__ dst, int E, int N) {
    int e = blockIdx.x * blockDim.x + threadIdx.x;
    if (e < E) {
        int p = atomicAdd(&g_cur[dst[e]], 1);
        g_eidx[p] = e;
    }
    if (e < N) g_cnt[e] = 0;
}

// ------ gather-reduce: TWO warps per node, each 256 columns ---------------
// zero-degree: out row = tanh(bias) (fused zerofill)
__global__ void reduce_kernel(const float* __restrict__ x,
                              const float* __restrict__ eta,
                              const int* __restrict__ src,
                              const float* __restrict__ bias,
                              float* __restrict__ out, int N) {
    int gw = (blockIdx.x * blockDim.x + threadIdx.x) >> 5;
    int n = gw >> 1;
    if (n >= N) return;
    int half = gw & 1;
    int lane = threadIdx.x & 31;
    int colBase = half * 64;            // float4-unit offset into the 128-wide row
    int beg = g_off[n], end = g_off[n + 1];

    if (beg == end) {
        #pragma unroll
        for (int q = 0; q < 2; q++) {
            float4 b = __ldg((const float4*)bias + colBase + q * 32 + lane);
            b.x = tanh_fast(b.x); b.y = tanh_fast(b.y);
            b.z = tanh_fast(b.z); b.w = tanh_fast(b.w);
            ((float4*)(out + (size_t)n * C_DIM))[colBase + q * 32 + lane] = b;
        }
        return;
    }

    float4 a0[2], a1[2], a2[2];
    #pragma unroll
    for (int q = 0; q < 2; q++) {
        a0[q] = make_float4(0.f, 0.f, 0.f, 0.f);
        a1[q] = a0[q];
        a2[q] = a0[q];
    }
    for (int j = beg; j < end; j++) {
        int e = g_eidx[j];
        int s = __ldg(src + e);
        float e0 = __ldg(eta + e * 3 + 0);
        float e1 = __ldg(eta + e * 3 + 1);
        float e2 = __ldg(eta + e * 3 + 2);
        const float4* xr = (const float4*)x + (size_t)s * 128 + colBase;
        #pragma unroll
        for (int q = 0; q < 2; q++) {
            float4 xv = __ldg(xr + q * 32 + lane);
            a0[q].x += e0 * xv.x; a0[q].y += e0 * xv.y; a0[q].z += e0 * xv.z; a0[q].w += e0 * xv.w;
            a1[q].x += e1 * xv.x; a1[q].y += e1 * xv.y; a1[q].z += e1 * xv.z; a1[q].w += e1 * xv.w;
            a2[q].x += e2 * xv.x; a2[q].y += e2 * xv.y; a2[q].z += e2 * xv.z; a2[q].w += e2 * xv.w;
        }
    }
    size_t base = (size_t)g_cid[n] * K3;
    #pragma unroll
    for (int q = 0; q < 2; q++) {
        __half h0[4] = {__float2half(a0[q].x), __float2half(a0[q].y),
                        __float2half(a0[q].z), __float2half(a0[q].w)};
        __half h1[4] = {__float2half(a1[q].x), __float2half(a1[q].y),
                        __float2half(a1[q].z), __float2half(a1[q].w)};
        __half h2[4] = {__float2half(a2[q].x), __float2half(a2[q].y),
                        __float2half(a2[q].z), __float2half(a2[q].w)};
        int o = (colBase + q * 32 + lane) * 4;
        *(uint2*)(g_Mh + base + 0 * 512 + o) = *(uint2*)h0;
        *(uint2*)(g_Mh + base + 1 * 512 + o) = *(uint2*)h1;
        *(uint2*)(g_Mh + base + 2 * 512 + o) = *(uint2*)h2;
    }
}

// ---------------- prepW: tiled transpose, coalesced both sides -------------
__global__ void prepW_kernel(const float* __restrict__ W) {
    __shared__ float tile[32][33];
    int s  = blockIdx.z;
    int c0 = blockIdx.x * 32;
    int d0 = blockIdx.y * 32;
    int tx = threadIdx.x;
    int ty = threadIdx.y;
    #pragma unroll
    for (int q = 0; q < 4; q++) {
        int d = d0 + ty + q * 8;
        tile[ty + q * 8][tx] = W[(size_t)d * K3 + s * C_DIM + c0 + tx];
    }
    __syncthreads();
    #pragma unroll
    for (int q = 0; q < 4; q++) {
        int c = c0 + ty + q * 8;
        g_Bh[(size_t)c * K3 + s * D_DIM + d0 + tx] = __float2half(tile[tx][ty + q * 8]);
    }
}

// ------------------------------- GEMM --------------------------------------
// compacted rows: out[orig[m], c] = tanh( sum_k M[m,k]*Bt[c,k] + bias[c] )
// CTA tile 128(M) x 256(N), 512 threads / 16 warps (4m x 4n), warp tile 32x64
#define TM 128
#define TN 256
#define TK 64
#define ROWB 144
#define MAT_A (128 * ROWB)
#define MAT_B (256 * ROWB)
#define STAGE_BYTES (MAT_A + MAT_B)
#define NSTAGE 3
#define GEMM_SMEM (NSTAGE * STAGE_BYTES)

__global__ __launch_bounds__(512, 1)
void gemm_kernel(const float* __restrict__ bias, float* __restrict__ out) {
    const int Nc = g_Nc;
    const int mt = blockIdx.x >> 1;
    const int m0 = mt * TM;
    if (m0 >= Nc) return;            // compacted grid is data-dependent

    extern __shared__ char dsm[];
    const uint32_t sbase = smem_to_u32(dsm);

    const int tid  = threadIdx.x;
    const int lane = tid & 31;
    const int wid  = tid >> 5;
    const int wm   = wid & 3;          // 0..3 -> 32 rows each
    const int wn   = wid >> 2;         // 0..3 -> 64 cols each

    const int nt = blockIdx.x & 1;
    const int n0 = nt * TN;

    // ---- hoisted per-thread source pointers (2 A rows, 4 B rows) ----
    const char* aSrc[2];
    uint32_t    aOk[2];
    #pragma unroll
    for (int i = 0; i < 2; i++) {
        int idx = tid + i * 512;
        int row = idx >> 3;
        int ch  = idx & 7;
        int gr = m0 + row;
        aOk[i]  = (gr < Nc) ? 16u : 0u;
        aSrc[i] = (gr < Nc) ? (const char*)(g_Mh + (size_t)gr * K3) + ch * 16
                            : (const char*)g_Mh;
    }
    const char* bSrc[4];
    #pragma unroll
    for (int i = 0; i < 4; i++) {
        int idx = tid + i * 512;
        int row = idx >> 3;
        int ch  = idx & 7;
        int br = n0 + row;
        bSrc[i] = (const char*)(g_Bh + (size_t)br * K3) + ch * 16;
    }

    auto stage_off = [&](int s) { return sbase + (uint32_t)s * STAGE_BYTES; };

    auto load_stage = [&](int s, int kc) {
        uint32_t so = stage_off(s);
        int kbyte = kc * TK * 2;
        #pragma unroll
        for (int i = 0; i < 2; i++) {
            int idx = tid + i * 512;
            int row = idx >> 3;
            int ch  = idx & 7;
            uint32_t d = (uint32_t)(row * ROWB + ch * 16);
            cp_async16(so + d, aSrc[i] + kbyte, aOk[i]);
        }
        #pragma unroll
        for (int i = 0; i < 4; i++) {
            int idx = tid + i * 512;
            int row = idx >> 3;
            int ch  = idx & 7;
            uint32_t d = (uint32_t)(row * ROWB + ch * 16);
            cp_async16(so + MAT_A + d, bSrc[i] + kbyte, 16u);
        }
    };

    float acc[2][8][4];
    #pragma unroll
    for (int i = 0; i < 2; i++)
        #pragma unroll
        for (int j = 0; j < 8; j++)
            #pragma unroll
            for (int q = 0; q < 4; q++) acc[i][j][q] = 0.f;

    const uint32_t aRow = (uint32_t)(wm * 32 + (lane & 15));
    const uint32_t bRow = (uint32_t)(wn * 64 + (lane & 15));
    const uint32_t colB = (uint32_t)((lane >> 4) * 16);

    load_stage(0, 0);
    cp_commit();
    load_stage(1, 1);
    cp_commit();

    uint32_t a[2][2][4], bh[2][4][4];

    const int NKC = K3 / TK;   // 24
    int sidx = 0;
    for (int kc = 0; kc < NKC; kc++) {
        if (kc + 1 < NKC) cp_wait1(); else cp_wait0();
        __syncthreads();
        if (kc + 2 < NKC) {
            int s2 = sidx + 2; if (s2 >= NSTAGE) s2 -= NSTAGE;
            load_stage(s2, kc + 2);
            cp_commit();
        }

        uint32_t so = stage_off(sidx);
        uint32_t aB   = so + aRow * ROWB + colB;
        uint32_t bHiB = so + MAT_A + bRow * ROWB + colB;

        #pragma unroll
        for (int i = 0; i < 2; i++)
            ldsm_x4(a[0][i], aB + (uint32_t)(i * 16) * ROWB);
        #pragma unroll
        for (int g = 0; g < 4; g++)
            ldsm_x4(bh[0][g], bHiB + (uint32_t)(g * 16) * ROWB);

        #pragma unroll
        for (int k16 = 0; k16 < 4; k16++) {
            int cur = k16 & 1;
            int nxt = cur ^ 1;
            if (k16 < 3) {
                uint32_t kb = (uint32_t)((k16 + 1) * 32);
                #pragma unroll
                for (int i = 0; i < 2; i++)
                    ldsm_x4(a[nxt][i], aB + (uint32_t)(i * 16) * ROWB + kb);
                #pragma unroll
                for (int g = 0; g < 4; g++)
                    ldsm_x4(bh[nxt][g], bHiB + (uint32_t)(g * 16) * ROWB + kb);
            }
            #pragma unroll
            for (int g = 0; g < 4; g++)
                #pragma unroll
                for (int i = 0; i < 2; i++) {
                    mma16816(acc[i][2*g],   a[cur][i], bh[cur][g][0], bh[cur][g][2]);
                    mma16816(acc[i][2*g+1], a[cur][i], bh[cur][g][1], bh[cur][g][3]);
                }
        }
        sidx++; if (sidx >= NSTAGE) sidx = 0;
    }

    // ---------------- epilogue: bias + tanh, scatter via g_orig ------------
    int orow[2][2];
    #pragma unroll
    for (int i = 0; i < 2; i++) {
        int r0 = m0 + wm * 32 + i * 16 + (lane >> 2);
        int r1 = r0 + 8;
        orow[i][0] = (r0 < Nc) ? __ldg(g_orig + r0) : -1;
        orow[i][1] = (r1 < Nc) ? __ldg(g_orig + r1) : -1;
    }
    #pragma unroll
    for (int j = 0; j < 8; j++) {
        int col = n0 + wn * 64 + j * 8 + (lane & 3) * 2;
        float b0 = __ldg(bias + col);
        float b1 = __ldg(bias + col + 1);
        #pragma unroll
        for (int i = 0; i < 2; i++) {
            if (orow[i][0] >= 0) {
                float2 o;
                o.x = tanh_fast(acc[i][j][0] + b0);
                o.y = tanh_fast(acc[i][j][1] + b1);
                *(float2*)(out + (size_t)orow[i][0] * C_DIM + col) = o;
            }
            if (orow[i][1] >= 0) {
                float2 o;
                o.x = tanh_fast(acc[i][j][2] + b0);
                o.y = tanh_fast(acc[i][j][3] + b1);
                *(float2*)(out + (size_t)orow[i][1] * C_DIM + col) = o;
            }
        }
    }
}

// ------------------------------ launch -------------------------------------
extern "C" void kernel_launch(void* const* d_in, const int* in_sizes, int n_in,
                              void* d_out, int out_size) {
    const float* x    = (const float*)d_in[0];
    const float* W    = (const float*)d_in[1];
    const float* bias = (const float*)d_in[2];
    const float* eta  = (const float*)d_in[3];
    const int*   src  = (const int*)d_in[4];
    const int*   dst  = (const int*)d_in[5];
    float* out = (float*)d_out;

    int N = in_sizes[0] / D_DIM;
    int E = in_sizes[4];

    // one-time stream/event setup (first call is NOT captured)
    static cudaStream_t s1 = nullptr;
    static cudaEvent_t evStart, evEnd;
    static bool inited = false;
    if (!inited) {
        cudaStreamCreateWithFlags(&s1, cudaStreamNonBlocking);
        cudaEventCreateWithFlags(&evStart, cudaEventDisableTiming);
        cudaEventCreateWithFlags(&evEnd, cudaEventDisableTiming);
        cudaFuncSetAttribute(gemm_kernel,
                             cudaFuncAttributeMaxDynamicSharedMemorySize,
                             GEMM_SMEM);
        inited = true;
    }

    int maxEN = (E > N) ? E : N;

    // fork s1 at entry (prepW is independent of the CSR/reduce chain)
    cudaEventRecord(evStart, 0);
    cudaStreamWaitEvent(s1, evStart, 0);

    // s0: CSR build + reduce (reduce is launch slot 4 -> profiled by ncu)
    hist_kernel<<<(E + 255) / 256, 256>>>(dst, E);
    scan_kernel<<<1, 1024>>>(N);
    fill_kernel<<<(maxEN + 255) / 256, 256>>>(dst, E, N);
    reduce_kernel<<<(N * 64 + 255) / 256, 256>>>(x, eta, src, bias, out, N);

    // s1: B transpose, concurrent with the whole s0 chain
    dim3 tgrid(C_DIM / 32, D_DIM / 32, 3);
    prepW_kernel<<<tgrid, dim3(32, 8), 0, s1>>>(W);
    cudaEventRecord(evEnd, s1);

    // join: GEMM needs both reduce (s0) and prepW (s1)
    cudaStreamWaitEvent(0, evEnd, 0);
    int mtiles = (N + TM - 1) / TM;       // worst-case grid; CTAs past g_Nc exit
    gemm_kernel<<<mtiles * 2, 512, GEMM_SMEM>>>(bias, out);
}

// round 12
// speedup vs baseline: 1.5841x; 1.5832x over previous
#include <cuda_runtime.h>
#include <cuda_fp16.h>
#include <cstdint>

#define D_DIM 512
#define C_DIM 512
#define K3    1536
#define MAXN  100000
#define MAXE  100000
#define NBMAX 512     // max scan blocks (ceil(100000/512)=196)

// ------------------------------ scratch ------------------------------------
__device__ __half g_Mh[(size_t)MAXN * K3];   // [Nc][1536] fp16 (compacted rows)
__device__ __half g_Bh[C_DIM * K3];          // [c][k] row-major fp16
__device__ int g_cnt[MAXN];                  // in-degree (re-zeroed each run)
__device__ int g_off[MAXN + 1];
__device__ int g_cur[MAXN];
__device__ int g_eidx[MAXE];
__device__ int g_cid[MAXN];                  // exclusive prefix of nonzero rows
__device__ int g_orig[MAXN];                 // compact row -> node
__device__ int g_Nc;                         // number of non-empty rows
__device__ int g_blkA[NBMAX];
__device__ int g_blkB[NBMAX];

// ------------------------------ helpers ------------------------------------
__device__ __forceinline__ uint32_t smem_to_u32(const void* smem_ptr) {
    uint32_t addr;
    asm("{ .reg .u64 tmp; cvta.to.shared.u64 tmp, %1; cvt.u32.u64 %0, tmp; }"
        : "=r"(addr) : "l"(smem_ptr));
    return addr;
}

__device__ __forceinline__ void cp_async16(uint32_t dst, const void* src, uint32_t src_bytes) {
    asm volatile("cp.async.cg.shared.global [%0], [%1], 16, %2;"
                 :: "r"(dst), "l"(src), "r"(src_bytes));
}
__device__ __forceinline__ void cp_commit() {
    asm volatile("cp.async.commit_group;" ::: "memory");
}
__device__ __forceinline__ void cp_wait1() {
    asm volatile("cp.async.wait_group 1;" ::: "memory");
}
__device__ __forceinline__ void cp_wait0() {
    asm volatile("cp.async.wait_group 0;" ::: "memory");
}

__device__ __forceinline__ void ldsm_x4(uint32_t* r, uint32_t addr) {
    asm volatile("ldmatrix.sync.aligned.m8n8.x4.shared.b16 {%0,%1,%2,%3}, [%4];"
                 : "=r"(r[0]), "=r"(r[1]), "=r"(r[2]), "=r"(r[3]) : "r"(addr));
}

__device__ __forceinline__ void mma16816(float* d, const uint32_t* a, uint32_t b0, uint32_t b1) {
    asm volatile("mma.sync.aligned.m16n8k16.row.col.f32.f16.f16.f32 "
                 "{%0,%1,%2,%3}, {%4,%5,%6,%7}, {%8,%9}, {%0,%1,%2,%3};"
                 : "+f"(d[0]), "+f"(d[1]), "+f"(d[2]), "+f"(d[3])
                 : "r"(a[0]), "r"(a[1]), "r"(a[2]), "r"(a[3]), "r"(b0), "r"(b1));
}

__device__ __forceinline__ float tanh_fast(float x) {
    float y;
    asm("tanh.approx.f32 %0, %1;" : "=f"(y) : "f"(x));
    return y;
}

// ------------------------------ CSR build ----------------------------------
__global__ void hist_kernel(const int* __restrict__ dst, int E) {
    int e = blockIdx.x * blockDim.x + threadIdx.x;
    if (e < E) atomicAdd(&g_cnt[dst[e]], 1);
}

// scan1: block-local inclusive scans of (cnt, cnt>0), 512 elems/block.
// writes LOCAL exclusive prefixes into g_off/g_cid and block totals.
__global__ void scan1_kernel(int N) {
    __shared__ int sA[512];
    __shared__ int sB[512];
    int t = threadIdx.x;
    int i = blockIdx.x * 512 + t;
    int c = (i < N) ? g_cnt[i] : 0;
    int b = (c > 0) ? 1 : 0;
    sA[t] = c; sB[t] = b;
    __syncthreads();
    #pragma unroll
    for (int off = 1; off < 512; off <<= 1) {
        int vA = sA[t], vB = sB[t];
        int oA = (t >= off) ? sA[t - off] : 0;
        int oB = (t >= off) ? sB[t - off] : 0;
        __syncthreads();
        sA[t] = vA + oA; sB[t] = vB + oB;
        __syncthreads();
    }
    if (i < N) {
        g_off[i] = sA[t] - c;    // local exclusive
        g_cid[i] = sB[t] - b;
    }
    if (t == 511) {
        g_blkA[blockIdx.x] = sA[511];
        g_blkB[blockIdx.x] = sB[511];
    }
}

// scan3: every block redundantly scans the block totals, then finalizes
// g_off/g_cur/g_cid/g_orig for its 512 elements. Also writes g_off[N], g_Nc.
__global__ void scan3_kernel(int N, int NB) {
    __shared__ int sA[512];
    __shared__ int sB[512];
    int t = threadIdx.x;
    sA[t] = (t < NB) ? g_blkA[t] : 0;
    sB[t] = (t < NB) ? g_blkB[t] : 0;
    __syncthreads();
    #pragma unroll
    for (int off = 1; off < 512; off <<= 1) {
        int vA = sA[t], vB = sB[t];
        int oA = (t >= off) ? sA[t - off] : 0;
        int oB = (t >= off) ? sB[t - off] : 0;
        __syncthreads();
        sA[t] = vA + oA; sB[t] = vB + oB;
        __syncthreads();
    }
    int mb = blockIdx.x;
    int offA = (mb > 0) ? sA[mb - 1] : 0;
    int offB = (mb > 0) ? sB[mb - 1] : 0;
    int totA = sA[NB - 1];
    int totB = sB[NB - 1];
    int i = mb * 512 + t;
    if (i < N) {
        int c = g_cnt[i];
        int eo = offA + g_off[i];
        g_off[i] = eo;
        g_cur[i] = eo;
        int cid = offB + g_cid[i];
        g_cid[i] = cid;
        if (c > 0) g_orig[cid] = i;
    }
    if (mb == 0 && t == 0) {
        g_off[N] = totA;
        g_Nc = totB;
    }
}

// fill edge lists; ALSO re-zero g_cnt for the next graph replay
__global__ void fill_kernel(const int* __restrict__ dst, int E, int N) {
    int e = blockIdx.x * blockDim.x + threadIdx.x;
    if (e < E) {
        int p = atomicAdd(&g_cur[dst[e]], 1);
        g_eidx[p] = e;
    }
    if (e < N) g_cnt[e] = 0;
}

// ------ gather-reduce: TWO warps per node, each 256 columns ---------------
// zero-degree: out row = tanh(bias) (fused zerofill)
__global__ void reduce_kernel(const float* __restrict__ x,
                              const float* __restrict__ eta,
                              const int* __restrict__ src,
                              const float* __restrict__ bias,
                              float* __restrict__ out, int N) {
    int gw = (blockIdx.x * blockDim.x + threadIdx.x) >> 5;
    int n = gw >> 1;
    if (n >= N) return;
    int half = gw & 1;
    int lane = threadIdx.x & 31;
    int colBase = half * 64;            // float4-unit offset into the 128-wide row
    int beg = g_off[n], end = g_off[n + 1];

    if (beg == end) {
        #pragma unroll
        for (int q = 0; q < 2; q++) {
            float4 b = __ldg((const float4*)bias + colBase + q * 32 + lane);
            b.x = tanh_fast(b.x); b.y = tanh_fast(b.y);
            b.z = tanh_fast(b.z); b.w = tanh_fast(b.w);
            ((float4*)(out + (size_t)n * C_DIM))[colBase + q * 32 + lane] = b;
        }
        return;
    }

    float4 a0[2], a1[2], a2[2];
    #pragma unroll
    for (int q = 0; q < 2; q++) {
        a0[q] = make_float4(0.f, 0.f, 0.f, 0.f);
        a1[q] = a0[q];
        a2[q] = a0[q];
    }
    for (int j = beg; j < end; j++) {
        int e = g_eidx[j];
        int s = __ldg(src + e);
        float e0 = __ldg(eta + e * 3 + 0);
        float e1 = __ldg(eta + e * 3 + 1);
        float e2 = __ldg(eta + e * 3 + 2);
        const float4* xr = (const float4*)x + (size_t)s * 128 + colBase;
        #pragma unroll
        for (int q = 0; q < 2; q++) {
            float4 xv = __ldg(xr + q * 32 + lane);
            a0[q].x += e0 * xv.x; a0[q].y += e0 * xv.y; a0[q].z += e0 * xv.z; a0[q].w += e0 * xv.w;
            a1[q].x += e1 * xv.x; a1[q].y += e1 * xv.y; a1[q].z += e1 * xv.z; a1[q].w += e1 * xv.w;
            a2[q].x += e2 * xv.x; a2[q].y += e2 * xv.y; a2[q].z += e2 * xv.z; a2[q].w += e2 * xv.w;
        }
    }
    size_t base = (size_t)g_cid[n] * K3;
    #pragma unroll
    for (int q = 0; q < 2; q++) {
        __half h0[4] = {__float2half(a0[q].x), __float2half(a0[q].y),
                        __float2half(a0[q].z), __float2half(a0[q].w)};
        __half h1[4] = {__float2half(a1[q].x), __float2half(a1[q].y),
                        __float2half(a1[q].z), __float2half(a1[q].w)};
        __half h2[4] = {__float2half(a2[q].x), __float2half(a2[q].y),
                        __float2half(a2[q].z), __float2half(a2[q].w)};
        int o = (colBase + q * 32 + lane) * 4;
        *(uint2*)(g_Mh + base + 0 * 512 + o) = *(uint2*)h0;
        *(uint2*)(g_Mh + base + 1 * 512 + o) = *(uint2*)h1;
        *(uint2*)(g_Mh + base + 2 * 512 + o) = *(uint2*)h2;
    }
}

// ---------------- prepW: tiled transpose, coalesced both sides -------------
__global__ void prepW_kernel(const float* __restrict__ W) {
    __shared__ float tile[32][33];
    int s  = blockIdx.z;
    int c0 = blockIdx.x * 32;
    int d0 = blockIdx.y * 32;
    int tx = threadIdx.x;
    int ty = threadIdx.y;
    #pragma unroll
    for (int q = 0; q < 4; q++) {
        int d = d0 + ty + q * 8;
        tile[ty + q * 8][tx] = W[(size_t)d * K3 + s * C_DIM + c0 + tx];
    }
    __syncthreads();
    #pragma unroll
    for (int q = 0; q < 4; q++) {
        int c = c0 + ty + q * 8;
        g_Bh[(size_t)c * K3 + s * D_DIM + d0 + tx] = __float2half(tile[tx][ty + q * 8]);
    }
}

// ------------------------------- GEMM --------------------------------------
// compacted rows: out[orig[m], c] = tanh( sum_k M[m,k]*Bt[c,k] + bias[c] )
// CTA tile 128(M) x 256(N), 512 threads / 16 warps (4m x 4n), warp tile 32x64
#define TM 128
#define TN 256
#define TK 64
#define ROWB 144
#define MAT_A (128 * ROWB)
#define MAT_B (256 * ROWB)
#define STAGE_BYTES (MAT_A + MAT_B)
#define NSTAGE 3
#define GEMM_SMEM (NSTAGE * STAGE_BYTES)

__global__ __launch_bounds__(512, 1)
void gemm_kernel(const float* __restrict__ bias, float* __restrict__ out) {
    const int Nc = g_Nc;
    const int mt = blockIdx.x >> 1;
    const int m0 = mt * TM;
    if (m0 >= Nc) return;            // compacted grid is data-dependent

    extern __shared__ char dsm[];
    const uint32_t sbase = smem_to_u32(dsm);

    const int tid  = threadIdx.x;
    const int lane = tid & 31;
    const int wid  = tid >> 5;
    const int wm   = wid & 3;          // 0..3 -> 32 rows each
    const int wn   = wid >> 2;         // 0..3 -> 64 cols each

    const int nt = blockIdx.x & 1;
    const int n0 = nt * TN;

    // ---- hoisted per-thread source pointers (2 A rows, 4 B rows) ----
    const char* aSrc[2];
    uint32_t    aOk[2];
    #pragma unroll
    for (int i = 0; i < 2; i++) {
        int idx = tid + i * 512;
        int row = idx >> 3;
        int ch  = idx & 7;
        int gr = m0 + row;
        aOk[i]  = (gr < Nc) ? 16u : 0u;
        aSrc[i] = (gr < Nc) ? (const char*)(g_Mh + (size_t)gr * K3) + ch * 16
                            : (const char*)g_Mh;
    }
    const char* bSrc[4];
    #pragma unroll
    for (int i = 0; i < 4; i++) {
        int idx = tid + i * 512;
        int row = idx >> 3;
        int ch  = idx & 7;
        int br = n0 + row;
        bSrc[i] = (const char*)(g_Bh + (size_t)br * K3) + ch * 16;
    }

    auto stage_off = [&](int s) { return sbase + (uint32_t)s * STAGE_BYTES; };

    auto load_stage = [&](int s, int kc) {
        uint32_t so = stage_off(s);
        int kbyte = kc * TK * 2;
        #pragma unroll
        for (int i = 0; i < 2; i++) {
            int idx = tid + i * 512;
            int row = idx >> 3;
            int ch  = idx & 7;
            uint32_t d = (uint32_t)(row * ROWB + ch * 16);
            cp_async16(so + d, aSrc[i] + kbyte, aOk[i]);
        }
        #pragma unroll
        for (int i = 0; i < 4; i++) {
            int idx = tid + i * 512;
            int row = idx >> 3;
            int ch  = idx & 7;
            uint32_t d = (uint32_t)(row * ROWB + ch * 16);
            cp_async16(so + MAT_A + d, bSrc[i] + kbyte, 16u);
        }
    };

    float acc[2][8][4];
    #pragma unroll
    for (int i = 0; i < 2; i++)
        #pragma unroll
        for (int j = 0; j < 8; j++)
            #pragma unroll
            for (int q = 0; q < 4; q++) acc[i][j][q] = 0.f;

    const uint32_t aRow = (uint32_t)(wm * 32 + (lane & 15));
    const uint32_t bRow = (uint32_t)(wn * 64 + (lane & 15));
    const uint32_t colB = (uint32_t)((lane >> 4) * 16);

    load_stage(0, 0);
    cp_commit();
    load_stage(1, 1);
    cp_commit();

    uint32_t a[2][2][4], bh[2][4][4];

    const int NKC = K3 / TK;   // 24
    int sidx = 0;
    for (int kc = 0; kc < NKC; kc++) {
        if (kc + 1 < NKC) cp_wait1(); else cp_wait0();
        __syncthreads();
        if (kc + 2 < NKC) {
            int s2 = sidx + 2; if (s2 >= NSTAGE) s2 -= NSTAGE;
            load_stage(s2, kc + 2);
            cp_commit();
        }

        uint32_t so = stage_off(sidx);
        uint32_t aB   = so + aRow * ROWB + colB;
        uint32_t bHiB = so + MAT_A + bRow * ROWB + colB;

        #pragma unroll
        for (int i = 0; i < 2; i++)
            ldsm_x4(a[0][i], aB + (uint32_t)(i * 16) * ROWB);
        #pragma unroll
        for (int g = 0; g < 4; g++)
            ldsm_x4(bh[0][g], bHiB + (uint32_t)(g * 16) * ROWB);

        #pragma unroll
        for (int k16 = 0; k16 < 4; k16++) {
            int cur = k16 & 1;
            int nxt = cur ^ 1;
            if (k16 < 3) {
                uint32_t kb = (uint32_t)((k16 + 1) * 32);
                #pragma unroll
                for (int i = 0; i < 2; i++)
                    ldsm_x4(a[nxt][i], aB + (uint32_t)(i * 16) * ROWB + kb);
                #pragma unroll
                for (int g = 0; g < 4; g++)
                    ldsm_x4(bh[nxt][g], bHiB + (uint32_t)(g * 16) * ROWB + kb);
            }
            #pragma unroll
            for (int g = 0; g < 4; g++)
                #pragma unroll
                for (int i = 0; i < 2; i++) {
                    mma16816(acc[i][2*g],   a[cur][i], bh[cur][g][0], bh[cur][g][2]);
                    mma16816(acc[i][2*g+1], a[cur][i], bh[cur][g][1], bh[cur][g][3]);
                }
        }
        sidx++; if (sidx >= NSTAGE) sidx = 0;
    }

    // ---------------- epilogue: bias + tanh, scatter via g_orig ------------
    int orow[2][2];
    #pragma unroll
    for (int i = 0; i < 2; i++) {
        int r0 = m0 + wm * 32 + i * 16 + (lane >> 2);
        int r1 = r0 + 8;
        orow[i][0] = (r0 < Nc) ? __ldg(g_orig + r0) : -1;
        orow[i][1] = (r1 < Nc) ? __ldg(g_orig + r1) : -1;
    }
    #pragma unroll
    for (int j = 0; j < 8; j++) {
        int col = n0 + wn * 64 + j * 8 + (lane & 3) * 2;
        float b0 = __ldg(bias + col);
        float b1 = __ldg(bias + col + 1);
        #pragma unroll
        for (int i = 0; i < 2; i++) {
            if (orow[i][0] >= 0) {
                float2 o;
                o.x = tanh_fast(acc[i][j][0] + b0);
                o.y = tanh_fast(acc[i][j][1] + b1);
                *(float2*)(out + (size_t)orow[i][0] * C_DIM + col) = o;
            }
            if (orow[i][1] >= 0) {
                float2 o;
                o.x = tanh_fast(acc[i][j][2] + b0);
                o.y = tanh_fast(acc[i][j][3] + b1);
                *(float2*)(out + (size_t)orow[i][1] * C_DIM + col) = o;
            }
        }
    }
}

// ------------------------------ launch -------------------------------------
extern "C" void kernel_launch(void* const* d_in, const int* in_sizes, int n_in,
                              void* d_out, int out_size) {
    const float* x    = (const float*)d_in[0];
    const float* W    = (const float*)d_in[1];
    const float* bias = (const float*)d_in[2];
    const float* eta  = (const float*)d_in[3];
    const int*   src  = (const int*)d_in[4];
    const int*   dst  = (const int*)d_in[5];
    float* out = (float*)d_out;

    int N = in_sizes[0] / D_DIM;
    int E = in_sizes[4];

    cudaFuncSetAttribute(gemm_kernel,
                         cudaFuncAttributeMaxDynamicSharedMemorySize,
                         GEMM_SMEM);

    int maxEN = (E > N) ? E : N;
    int NB = (N + 511) / 512;          // scan blocks (<= NBMAX)

    // single stream, shortest serial chain
    hist_kernel<<<(E + 255) / 256, 256>>>(dst, E);
    scan1_kernel<<<NB, 512>>>(N);
    scan3_kernel<<<NB, 512>>>(N, NB);
    fill_kernel<<<(maxEN + 255) / 256, 256>>>(dst, E, N);
    reduce_kernel<<<(N * 64 + 255) / 256, 256>>>(x, eta, src, bias, out, N);
    dim3 tgrid(C_DIM / 32, D_DIM / 32, 3);
    prepW_kernel<<<tgrid, dim3(32, 8)>>>(W);
    int mtiles = (N + TM - 1) / TM;    // worst-case grid; CTAs past g_Nc exit
    gemm_kernel<<<mtiles * 2, 512, GEMM_SMEM>>>(bias, out);
}

// round 13
// speedup vs baseline: 1.5889x; 1.0031x over previous
#include <cuda_runtime.h>
#include <cuda_fp16.h>
#include <cstdint>

#define D_DIM 512
#define C_DIM 512
#define K3    1536
#define MAXN  100000
#define MAXE  100000
#define NBMAX 512     // max scan blocks (ceil(100000/512)=196)

// ------------------------------ scratch ------------------------------------
__device__ __half g_Mh[(size_t)MAXN * K3];   // [Nc][1536] fp16 (compacted rows)
__device__ __half g_Bh[C_DIM * K3];          // [c][k] row-major fp16
__device__ int g_cnt[MAXN];                  // in-degree (re-zeroed each run)
__device__ int g_off[MAXN + 1];
__device__ int g_cur[MAXN];
__device__ int    g_esrc[MAXE];              // CSR-ordered src node per edge slot
__device__ float4 g_eeta4[MAXE];             // CSR-ordered eta triple per edge slot
__device__ int g_cid[MAXN];                  // exclusive prefix of nonzero rows
__device__ int g_orig[MAXN];                 // compact row -> node
__device__ int g_Nc;                         // number of non-empty rows
__device__ int g_blkA[NBMAX];
__device__ int g_blkB[NBMAX];

// ------------------------------ helpers ------------------------------------
__device__ __forceinline__ uint32_t smem_to_u32(const void* smem_ptr) {
    uint32_t addr;
    asm("{ .reg .u64 tmp; cvta.to.shared.u64 tmp, %1; cvt.u32.u64 %0, tmp; }"
        : "=r"(addr) : "l"(smem_ptr));
    return addr;
}

__device__ __forceinline__ void cp_async16(uint32_t dst, const void* src, uint32_t src_bytes) {
    asm volatile("cp.async.cg.shared.global [%0], [%1], 16, %2;"
                 :: "r"(dst), "l"(src), "r"(src_bytes));
}
__device__ __forceinline__ void cp_commit() {
    asm volatile("cp.async.commit_group;" ::: "memory");
}
__device__ __forceinline__ void cp_wait1() {
    asm volatile("cp.async.wait_group 1;" ::: "memory");
}
__device__ __forceinline__ void cp_wait0() {
    asm volatile("cp.async.wait_group 0;" ::: "memory");
}

__device__ __forceinline__ void ldsm_x4(uint32_t* r, uint32_t addr) {
    asm volatile("ldmatrix.sync.aligned.m8n8.x4.shared.b16 {%0,%1,%2,%3}, [%4];"
                 : "=r"(r[0]), "=r"(r[1]), "=r"(r[2]), "=r"(r[3]) : "r"(addr));
}

__device__ __forceinline__ void mma16816(float* d, const uint32_t* a, uint32_t b0, uint32_t b1) {
    asm volatile("mma.sync.aligned.m16n8k16.row.col.f32.f16.f16.f32 "
                 "{%0,%1,%2,%3}, {%4,%5,%6,%7}, {%8,%9}, {%0,%1,%2,%3};"
                 : "+f"(d[0]), "+f"(d[1]), "+f"(d[2]), "+f"(d[3])
                 : "r"(a[0]), "r"(a[1]), "r"(a[2]), "r"(a[3]), "r"(b0), "r"(b1));
}

__device__ __forceinline__ float tanh_fast(float x) {
    float y;
    asm("tanh.approx.f32 %0, %1;" : "=f"(y) : "f"(x));
    return y;
}

// ------------------------------ CSR build ----------------------------------
__global__ void hist_kernel(const int* __restrict__ dst, int E) {
    int e = blockIdx.x * blockDim.x + threadIdx.x;
    if (e < E) atomicAdd(&g_cnt[dst[e]], 1);
}

// scan1: block-local inclusive scans of (cnt, cnt>0), 512 elems/block.
__global__ void scan1_kernel(int N) {
    __shared__ int sA[512];
    __shared__ int sB[512];
    int t = threadIdx.x;
    int i = blockIdx.x * 512 + t;
    int c = (i < N) ? g_cnt[i] : 0;
    int b = (c > 0) ? 1 : 0;
    sA[t] = c; sB[t] = b;
    __syncthreads();
    #pragma unroll
    for (int off = 1; off < 512; off <<= 1) {
        int vA = sA[t], vB = sB[t];
        int oA = (t >= off) ? sA[t - off] : 0;
        int oB = (t >= off) ? sB[t - off] : 0;
        __syncthreads();
        sA[t] = vA + oA; sB[t] = vB + oB;
        __syncthreads();
    }
    if (i < N) {
        g_off[i] = sA[t] - c;    // local exclusive
        g_cid[i] = sB[t] - b;
    }
    if (t == 511) {
        g_blkA[blockIdx.x] = sA[511];
        g_blkB[blockIdx.x] = sB[511];
    }
}

// scan3: redundant block-total scan + finalize offsets/compaction.
__global__ void scan3_kernel(int N, int NB) {
    __shared__ int sA[512];
    __shared__ int sB[512];
    int t = threadIdx.x;
    sA[t] = (t < NB) ? g_blkA[t] : 0;
    sB[t] = (t < NB) ? g_blkB[t] : 0;
    __syncthreads();
    #pragma unroll
    for (int off = 1; off < 512; off <<= 1) {
        int vA = sA[t], vB = sB[t];
        int oA = (t >= off) ? sA[t - off] : 0;
        int oB = (t >= off) ? sB[t - off] : 0;
        __syncthreads();
        sA[t] = vA + oA; sB[t] = vB + oB;
        __syncthreads();
    }
    int mb = blockIdx.x;
    int offA = (mb > 0) ? sA[mb - 1] : 0;
    int offB = (mb > 0) ? sB[mb - 1] : 0;
    int totA = sA[NB - 1];
    int totB = sB[NB - 1];
    int i = mb * 512 + t;
    if (i < N) {
        int c = g_cnt[i];
        int eo = offA + g_off[i];
        g_off[i] = eo;
        g_cur[i] = eo;
        int cid = offB + g_cid[i];
        g_cid[i] = cid;
        if (c > 0) g_orig[cid] = i;
    }
    if (mb == 0 && t == 0) {
        g_off[N] = totA;
        g_Nc = totB;
    }
}

// fill: scatter edges into CSR order, PRE-EXPANDING src + eta per slot
// (kills one indirection level in reduce). Also re-zeroes g_cnt for replay.
__global__ void fill_kernel(const int* __restrict__ dst,
                            const int* __restrict__ src,
                            const float* __restrict__ eta, int E, int N) {
    int e = blockIdx.x * blockDim.x + threadIdx.x;
    if (e < E) {
        int p = atomicAdd(&g_cur[dst[e]], 1);
        g_esrc[p] = src[e];
        g_eeta4[p] = make_float4(__ldg(eta + e * 3 + 0),
                                 __ldg(eta + e * 3 + 1),
                                 __ldg(eta + e * 3 + 2), 0.f);
    }
    if (e < N) g_cnt[e] = 0;
}

// ------ gather-reduce: TWO warps per node, each 256 columns ---------------
// direct esrc/eeta arrays + software-pipelined next-src load.
__global__ void reduce_kernel(const float* __restrict__ x,
                              const float* __restrict__ bias,
                              float* __restrict__ out, int N) {
    int gw = (blockIdx.x * blockDim.x + threadIdx.x) >> 5;
    int n = gw >> 1;
    if (n >= N) return;
    int half = gw & 1;
    int lane = threadIdx.x & 31;
    int colBase = half * 64;            // float4-unit offset into the 128-wide row
    int beg = g_off[n], end = g_off[n + 1];

    if (beg == end) {
        #pragma unroll
        for (int q = 0; q < 2; q++) {
            float4 b = __ldg((const float4*)bias + colBase + q * 32 + lane);
            b.x = tanh_fast(b.x); b.y = tanh_fast(b.y);
            b.z = tanh_fast(b.z); b.w = tanh_fast(b.w);
            ((float4*)(out + (size_t)n * C_DIM))[colBase + q * 32 + lane] = b;
        }
        return;
    }

    float4 a0[2], a1[2], a2[2];
    #pragma unroll
    for (int q = 0; q < 2; q++) {
        a0[q] = make_float4(0.f, 0.f, 0.f, 0.f);
        a1[q] = a0[q];
        a2[q] = a0[q];
    }
    int s = __ldg(g_esrc + beg);                 // pipeline head
    for (int j = beg; j < end; j++) {
        int sNext = (j + 1 < end) ? __ldg(g_esrc + j + 1) : 0;
        float4 ev = __ldg(g_eeta4 + j);
        const float4* xr = (const float4*)x + (size_t)s * 128 + colBase;
        #pragma unroll
        for (int q = 0; q < 2; q++) {
            float4 xv = __ldg(xr + q * 32 + lane);
            a0[q].x += ev.x * xv.x; a0[q].y += ev.x * xv.y; a0[q].z += ev.x * xv.z; a0[q].w += ev.x * xv.w;
            a1[q].x += ev.y * xv.x; a1[q].y += ev.y * xv.y; a1[q].z += ev.y * xv.z; a1[q].w += ev.y * xv.w;
            a2[q].x += ev.z * xv.x; a2[q].y += ev.z * xv.y; a2[q].z += ev.z * xv.z; a2[q].w += ev.z * xv.w;
        }
        s = sNext;
    }
    size_t base = (size_t)g_cid[n] * K3;
    #pragma unroll
    for (int q = 0; q < 2; q++) {
        __half h0[4] = {__float2half(a0[q].x), __float2half(a0[q].y),
                        __float2half(a0[q].z), __float2half(a0[q].w)};
        __half h1[4] = {__float2half(a1[q].x), __float2half(a1[q].y),
                        __float2half(a1[q].z), __float2half(a1[q].w)};
        __half h2[4] = {__float2half(a2[q].x), __float2half(a2[q].y),
                        __float2half(a2[q].z), __float2half(a2[q].w)};
        int o = (colBase + q * 32 + lane) * 4;
        *(uint2*)(g_Mh + base + 0 * 512 + o) = *(uint2*)h0;
        *(uint2*)(g_Mh + base + 1 * 512 + o) = *(uint2*)h1;
        *(uint2*)(g_Mh + base + 2 * 512 + o) = *(uint2*)h2;
    }
}

// ---------------- prepW: tiled transpose, coalesced both sides -------------
__global__ void prepW_kernel(const float* __restrict__ W) {
    __shared__ float tile[32][33];
    int s  = blockIdx.z;
    int c0 = blockIdx.x * 32;
    int d0 = blockIdx.y * 32;
    int tx = threadIdx.x;
    int ty = threadIdx.y;
    #pragma unroll
    for (int q = 0; q < 4; q++) {
        int d = d0 + ty + q * 8;
        tile[ty + q * 8][tx] = W[(size_t)d * K3 + s * C_DIM + c0 + tx];
    }
    __syncthreads();
    #pragma unroll
    for (int q = 0; q < 4; q++) {
        int c = c0 + ty + q * 8;
        g_Bh[(size_t)c * K3 + s * D_DIM + d0 + tx] = __float2half(tile[tx][ty + q * 8]);
    }
}

// ------------------------------- GEMM --------------------------------------
// compacted rows: out[orig[m], c] = tanh( sum_k M[m,k]*Bt[c,k] + bias[c] )
// CTA tile 128(M) x 256(N), 512 threads / 16 warps (4m x 4n), warp tile 32x64
#define TM 128
#define TN 256
#define TK 64
#define ROWB 144
#define MAT_A (128 * ROWB)
#define MAT_B (256 * ROWB)
#define STAGE_BYTES (MAT_A + MAT_B)
#define NSTAGE 3
#define GEMM_SMEM (NSTAGE * STAGE_BYTES)

__global__ __launch_bounds__(512, 1)
void gemm_kernel(const float* __restrict__ bias, float* __restrict__ out) {
    const int Nc = g_Nc;
    const int mt = blockIdx.x >> 1;
    const int m0 = mt * TM;
    if (m0 >= Nc) return;            // compacted grid is data-dependent

    extern __shared__ char dsm[];
    const uint32_t sbase = smem_to_u32(dsm);

    const int tid  = threadIdx.x;
    const int lane = tid & 31;
    const int wid  = tid >> 5;
    const int wm   = wid & 3;          // 0..3 -> 32 rows each
    const int wn   = wid >> 2;         // 0..3 -> 64 cols each

    const int nt = blockIdx.x & 1;
    const int n0 = nt * TN;

    // ---- hoisted per-thread source pointers (2 A rows, 4 B rows) ----
    const char* aSrc[2];
    uint32_t    aOk[2];
    #pragma unroll
    for (int i = 0; i < 2; i++) {
        int idx = tid + i * 512;
        int row = idx >> 3;
        int ch  = idx & 7;
        int gr = m0 + row;
        aOk[i]  = (gr < Nc) ? 16u : 0u;
        aSrc[i] = (gr < Nc) ? (const char*)(g_Mh + (size_t)gr * K3) + ch * 16
                            : (const char*)g_Mh;
    }
    const char* bSrc[4];
    #pragma unroll
    for (int i = 0; i < 4; i++) {
        int idx = tid + i * 512;
        int row = idx >> 3;
        int ch  = idx & 7;
        int br = n0 + row;
        bSrc[i] = (const char*)(g_Bh + (size_t)br * K3) + ch * 16;
    }

    auto stage_off = [&](int s) { return sbase + (uint32_t)s * STAGE_BYTES; };

    auto load_stage = [&](int s, int kc) {
        uint32_t so = stage_off(s);
        int kbyte = kc * TK * 2;
        #pragma unroll
        for (int i = 0; i < 2; i++) {
            int idx = tid + i * 512;
            int row = idx >> 3;
            int ch  = idx & 7;
            uint32_t d = (uint32_t)(row * ROWB + ch * 16);
            cp_async16(so + d, aSrc[i] + kbyte, aOk[i]);
        }
        #pragma unroll
        for (int i = 0; i < 4; i++) {
            int idx = tid + i * 512;
            int row = idx >> 3;
            int ch  = idx & 7;
            uint32_t d = (uint32_t)(row * ROWB + ch * 16);
            cp_async16(so + MAT_A + d, bSrc[i] + kbyte, 16u);
        }
    };

    float acc[2][8][4];
    #pragma unroll
    for (int i = 0; i < 2; i++)
        #pragma unroll
        for (int j = 0; j < 8; j++)
            #pragma unroll
            for (int q = 0; q < 4; q++) acc[i][j][q] = 0.f;

    const uint32_t aRow = (uint32_t)(wm * 32 + (lane & 15));
    const uint32_t bRow = (uint32_t)(wn * 64 + (lane & 15));
    const uint32_t colB = (uint32_t)((lane >> 4) * 16);

    load_stage(0, 0);
    cp_commit();
    load_stage(1, 1);
    cp_commit();

    uint32_t a[2][2][4], bh[2][4][4];

    const int NKC = K3 / TK;   // 24
    int sidx = 0;
    for (int kc = 0; kc < NKC; kc++) {
        if (kc + 1 < NKC) cp_wait1(); else cp_wait0();
        __syncthreads();
        if (kc + 2 < NKC) {
            int s2 = sidx + 2; if (s2 >= NSTAGE) s2 -= NSTAGE;
            load_stage(s2, kc + 2);
            cp_commit();
        }

        uint32_t so = stage_off(sidx);
        uint32_t aB   = so + aRow * ROWB + colB;
        uint32_t bHiB = so + MAT_A + bRow * ROWB + colB;

        #pragma unroll
        for (int i = 0; i < 2; i++)
            ldsm_x4(a[0][i], aB + (uint32_t)(i * 16) * ROWB);
        #pragma unroll
        for (int g = 0; g < 4; g++)
            ldsm_x4(bh[0][g], bHiB + (uint32_t)(g * 16) * ROWB);

        #pragma unroll
        for (int k16 = 0; k16 < 4; k16++) {
            int cur = k16 & 1;
            int nxt = cur ^ 1;
            if (k16 < 3) {
                uint32_t kb = (uint32_t)((k16 + 1) * 32);
                #pragma unroll
                for (int i = 0; i < 2; i++)
                    ldsm_x4(a[nxt][i], aB + (uint32_t)(i * 16) * ROWB + kb);
                #pragma unroll
                for (int g = 0; g < 4; g++)
                    ldsm_x4(bh[nxt][g], bHiB + (uint32_t)(g * 16) * ROWB + kb);
            }
            #pragma unroll
            for (int g = 0; g < 4; g++)
                #pragma unroll
                for (int i = 0; i < 2; i++) {
                    mma16816(acc[i][2*g],   a[cur][i], bh[cur][g][0], bh[cur][g][2]);
                    mma16816(acc[i][2*g+1], a[cur][i], bh[cur][g][1], bh[cur][g][3]);
                }
        }
        sidx++; if (sidx >= NSTAGE) sidx = 0;
    }

    // ---------------- epilogue: bias + tanh, scatter via g_orig ------------
    int orow[2][2];
    #pragma unroll
    for (int i = 0; i < 2; i++) {
        int r0 = m0 + wm * 32 + i * 16 + (lane >> 2);
        int r1 = r0 + 8;
        orow[i][0] = (r0 < Nc) ? __ldg(g_orig + r0) : -1;
        orow[i][1] = (r1 < Nc) ? __ldg(g_orig + r1) : -1;
    }
    #pragma unroll
    for (int j = 0; j < 8; j++) {
        int col = n0 + wn * 64 + j * 8 + (lane & 3) * 2;
        float b0 = __ldg(bias + col);
        float b1 = __ldg(bias + col + 1);
        #pragma unroll
        for (int i = 0; i < 2; i++) {
            if (orow[i][0] >= 0) {
                float2 o;
                o.x = tanh_fast(acc[i][j][0] + b0);
                o.y = tanh_fast(acc[i][j][1] + b1);
                *(float2*)(out + (size_t)orow[i][0] * C_DIM + col) = o;
            }
            if (orow[i][1] >= 0) {
                float2 o;
                o.x = tanh_fast(acc[i][j][2] + b0);
                o.y = tanh_fast(acc[i][j][3] + b1);
                *(float2*)(out + (size_t)orow[i][1] * C_DIM + col) = o;
            }
        }
    }
}

// ------------------------------ launch -------------------------------------
extern "C" void kernel_launch(void* const* d_in, const int* in_sizes, int n_in,
                              void* d_out, int out_size) {
    const float* x    = (const float*)d_in[0];
    const float* W    = (const float*)d_in[1];
    const float* bias = (const float*)d_in[2];
    const float* eta  = (const float*)d_in[3];
    const int*   src  = (const int*)d_in[4];
    const int*   dst  = (const int*)d_in[5];
    float* out = (float*)d_out;

    int N = in_sizes[0] / D_DIM;
    int E = in_sizes[4];

    cudaFuncSetAttribute(gemm_kernel,
                         cudaFuncAttributeMaxDynamicSharedMemorySize,
                         GEMM_SMEM);

    int maxEN = (E > N) ? E : N;
    int NB = (N + 511) / 512;          // scan blocks (<= NBMAX)

    // single stream, shortest serial chain
    hist_kernel<<<(E + 255) / 256, 256>>>(dst, E);
    scan1_kernel<<<NB, 512>>>(N);
    scan3_kernel<<<NB, 512>>>(N, NB);
    fill_kernel<<<(maxEN + 255) / 256, 256>>>(dst, src, eta, E, N);
    reduce_kernel<<<(N * 64 + 255) / 256, 256>>>(x, bias, out, N);
    dim3 tgrid(C_DIM / 32, D_DIM / 32, 3);
    prepW_kernel<<<tgrid, dim3(32, 8)>>>(W);
    int mtiles = (N + TM - 1) / TM;    // worst-case grid; CTAs past g_Nc exit
    gemm_kernel<<<mtiles * 2, 512, GEMM_SMEM>>>(bias, out);
}

// round 14
// speedup vs baseline: 1.6329x; 1.0277x over previous
#include <cuda_runtime.h>
#include <cuda_fp16.h>
#include <cstdint>

#define D_DIM 512
#define C_DIM 512
#define K3    1536
#define MAXN  100000
#define MAXE  100000
#define NBMAX 512     // max scan blocks (ceil(100000/512)=196)

// ------------------------------ scratch ------------------------------------
__device__ __half g_Mh[(size_t)MAXN * K3];   // [Nc][1536] fp16 (compacted rows)
__device__ __half g_Bh[C_DIM * K3];          // [c][k] row-major fp16
__device__ int g_cnt[MAXN];                  // in-degree (re-zeroed each run)
__device__ int g_off[MAXN + 1];
__device__ int g_cur[MAXN];
__device__ int    g_esrc[MAXE];              // CSR-ordered src node per edge slot
__device__ float4 g_eeta4[MAXE];             // CSR-ordered eta triple per edge slot
__device__ int g_cid[MAXN];                  // exclusive prefix of nonzero rows
__device__ int g_orig[MAXN];                 // compact row -> node
__device__ int g_Nc;                         // number of non-empty rows
__device__ int g_blkA[NBMAX];
__device__ int g_blkB[NBMAX];

// ------------------------------ helpers ------------------------------------
__device__ __forceinline__ uint32_t smem_to_u32(const void* smem_ptr) {
    uint32_t addr;
    asm("{ .reg .u64 tmp; cvta.to.shared.u64 tmp, %1; cvt.u32.u64 %0, tmp; }"
        : "=r"(addr) : "l"(smem_ptr));
    return addr;
}

__device__ __forceinline__ void cp_async16(uint32_t dst, const void* src, uint32_t src_bytes) {
    asm volatile("cp.async.cg.shared.global [%0], [%1], 16, %2;"
                 :: "r"(dst), "l"(src), "r"(src_bytes));
}
__device__ __forceinline__ void cp_commit() {
    asm volatile("cp.async.commit_group;" ::: "memory");
}
__device__ __forceinline__ void cp_wait2() {
    asm volatile("cp.async.wait_group 2;" ::: "memory");
}
__device__ __forceinline__ void cp_wait1() {
    asm volatile("cp.async.wait_group 1;" ::: "memory");
}
__device__ __forceinline__ void cp_wait0() {
    asm volatile("cp.async.wait_group 0;" ::: "memory");
}

__device__ __forceinline__ void ldsm_x4(uint32_t* r, uint32_t addr) {
    asm volatile("ldmatrix.sync.aligned.m8n8.x4.shared.b16 {%0,%1,%2,%3}, [%4];"
                 : "=r"(r[0]), "=r"(r[1]), "=r"(r[2]), "=r"(r[3]) : "r"(addr));
}

__device__ __forceinline__ void mma16816(float* d, const uint32_t* a, uint32_t b0, uint32_t b1) {
    asm volatile("mma.sync.aligned.m16n8k16.row.col.f32.f16.f16.f32 "
                 "{%0,%1,%2,%3}, {%4,%5,%6,%7}, {%8,%9}, {%0,%1,%2,%3};"
                 : "+f"(d[0]), "+f"(d[1]), "+f"(d[2]), "+f"(d[3])
                 : "r"(a[0]), "r"(a[1]), "r"(a[2]), "r"(a[3]), "r"(b0), "r"(b1));
}

__device__ __forceinline__ float tanh_fast(float x) {
    float y;
    asm("tanh.approx.f32 %0, %1;" : "=f"(y) : "f"(x));
    return y;
}

// -------------- fat kernel: prepW transpose (blocks 0..767) + hist ----------
// prepW: g_Bh[c*1536 + s*512 + d] = fp16(W[d*1536 + s*512 + c])
// hist: atomicAdd per edge (blocks 768..)
#define PREPW_BLOCKS 768
__global__ void histPrepW_kernel(const float* __restrict__ W,
                                 const int* __restrict__ dst, int E) {
    int b = blockIdx.x;
    int t = threadIdx.x;
    if (b < PREPW_BLOCKS) {
        __shared__ float tile[32][33];
        int s   = b >> 8;             // 0..2
        int rem = b & 255;
        int c0  = (rem & 15) * 32;
        int d0  = (rem >> 4) * 32;
        int tx = t & 31;
        int ty = t >> 5;              // 0..7
        #pragma unroll
        for (int q = 0; q < 4; q++) {
            int d = d0 + ty + q * 8;
            tile[ty + q * 8][tx] = W[(size_t)d * K3 + s * C_DIM + c0 + tx];
        }
        __syncthreads();
        #pragma unroll
        for (int q = 0; q < 4; q++) {
            int c = c0 + ty + q * 8;
            g_Bh[(size_t)c * K3 + s * D_DIM + d0 + tx] = __float2half(tile[tx][ty + q * 8]);
        }
    } else {
        int e = (b - PREPW_BLOCKS) * blockDim.x + t;
        if (e < E) atomicAdd(&g_cnt[dst[e]], 1);
    }
}

// scan1: block-local inclusive scans of (cnt, cnt>0), 512 elems/block.
__global__ void scan1_kernel(int N) {
    __shared__ int sA[512];
    __shared__ int sB[512];
    int t = threadIdx.x;
    int i = blockIdx.x * 512 + t;
    int c = (i < N) ? g_cnt[i] : 0;
    int b = (c > 0) ? 1 : 0;
    sA[t] = c; sB[t] = b;
    __syncthreads();
    #pragma unroll
    for (int off = 1; off < 512; off <<= 1) {
        int vA = sA[t], vB = sB[t];
        int oA = (t >= off) ? sA[t - off] : 0;
        int oB = (t >= off) ? sB[t - off] : 0;
        __syncthreads();
        sA[t] = vA + oA; sB[t] = vB + oB;
        __syncthreads();
    }
    if (i < N) {
        g_off[i] = sA[t] - c;    // local exclusive
        g_cid[i] = sB[t] - b;
    }
    if (t == 511) {
        g_blkA[blockIdx.x] = sA[511];
        g_blkB[blockIdx.x] = sB[511];
    }
}

// scan3: redundant block-total scan + finalize offsets/compaction.
__global__ void scan3_kernel(int N, int NB) {
    __shared__ int sA[512];
    __shared__ int sB[512];
    int t = threadIdx.x;
    sA[t] = (t < NB) ? g_blkA[t] : 0;
    sB[t] = (t < NB) ? g_blkB[t] : 0;
    __syncthreads();
    #pragma unroll
    for (int off = 1; off < 512; off <<= 1) {
        int vA = sA[t], vB = sB[t];
        int oA = (t >= off) ? sA[t - off] : 0;
        int oB = (t >= off) ? sB[t - off] : 0;
        __syncthreads();
        sA[t] = vA + oA; sB[t] = vB + oB;
        __syncthreads();
    }
    int mb = blockIdx.x;
    int offA = (mb > 0) ? sA[mb - 1] : 0;
    int offB = (mb > 0) ? sB[mb - 1] : 0;
    int totA = sA[NB - 1];
    int totB = sB[NB - 1];
    int i = mb * 512 + t;
    if (i < N) {
        int c = g_cnt[i];
        int eo = offA + g_off[i];
        g_off[i] = eo;
        g_cur[i] = eo;
        int cid = offB + g_cid[i];
        g_cid[i] = cid;
        if (c > 0) g_orig[cid] = i;
    }
    if (mb == 0 && t == 0) {
        g_off[N] = totA;
        g_Nc = totB;
    }
}

// fill: scatter edges into CSR order with pre-expanded src + eta.
// Also re-zeroes g_cnt for the next graph replay.
__global__ void fill_kernel(const int* __restrict__ dst,
                            const int* __restrict__ src,
                            const float* __restrict__ eta, int E, int N) {
    int e = blockIdx.x * blockDim.x + threadIdx.x;
    if (e < E) {
        int p = atomicAdd(&g_cur[dst[e]], 1);
        g_esrc[p] = src[e];
        g_eeta4[p] = make_float4(__ldg(eta + e * 3 + 0),
                                 __ldg(eta + e * 3 + 1),
                                 __ldg(eta + e * 3 + 2), 0.f);
    }
    if (e < N) g_cnt[e] = 0;
}

// ------ gather-reduce: TWO warps per node, each 256 columns ---------------
__global__ void reduce_kernel(const float* __restrict__ x,
                              const float* __restrict__ bias,
                              float* __restrict__ out, int N) {
    int gw = (blockIdx.x * blockDim.x + threadIdx.x) >> 5;
    int n = gw >> 1;
    if (n >= N) return;
    int half = gw & 1;
    int lane = threadIdx.x & 31;
    int colBase = half * 64;            // float4-unit offset into the 128-wide row
    int beg = g_off[n], end = g_off[n + 1];

    if (beg == end) {
        #pragma unroll
        for (int q = 0; q < 2; q++) {
            float4 b = __ldg((const float4*)bias + colBase + q * 32 + lane);
            b.x = tanh_fast(b.x); b.y = tanh_fast(b.y);
            b.z = tanh_fast(b.z); b.w = tanh_fast(b.w);
            ((float4*)(out + (size_t)n * C_DIM))[colBase + q * 32 + lane] = b;
        }
        return;
    }

    float4 a0[2], a1[2], a2[2];
    #pragma unroll
    for (int q = 0; q < 2; q++) {
        a0[q] = make_float4(0.f, 0.f, 0.f, 0.f);
        a1[q] = a0[q];
        a2[q] = a0[q];
    }
    int s = __ldg(g_esrc + beg);
    for (int j = beg; j < end; j++) {
        int sNext = (j + 1 < end) ? __ldg(g_esrc + j + 1) : 0;
        float4 ev = __ldg(g_eeta4 + j);
        const float4* xr = (const float4*)x + (size_t)s * 128 + colBase;
        #pragma unroll
        for (int q = 0; q < 2; q++) {
            float4 xv = __ldg(xr + q * 32 + lane);
            a0[q].x += ev.x * xv.x; a0[q].y += ev.x * xv.y; a0[q].z += ev.x * xv.z; a0[q].w += ev.x * xv.w;
            a1[q].x += ev.y * xv.x; a1[q].y += ev.y * xv.y; a1[q].z += ev.y * xv.z; a1[q].w += ev.y * xv.w;
            a2[q].x += ev.z * xv.x; a2[q].y += ev.z * xv.y; a2[q].z += ev.z * xv.z; a2[q].w += ev.z * xv.w;
        }
        s = sNext;
    }
    size_t base = (size_t)g_cid[n] * K3;
    #pragma unroll
    for (int q = 0; q < 2; q++) {
        __half h0[4] = {__float2half(a0[q].x), __float2half(a0[q].y),
                        __float2half(a0[q].z), __float2half(a0[q].w)};
        __half h1[4] = {__float2half(a1[q].x), __float2half(a1[q].y),
                        __float2half(a1[q].z), __float2half(a1[q].w)};
        __half h2[4] = {__float2half(a2[q].x), __float2half(a2[q].y),
                        __float2half(a2[q].z), __float2half(a2[q].w)};
        int o = (colBase + q * 32 + lane) * 4;
        *(uint2*)(g_Mh + base + 0 * 512 + o) = *(uint2*)h0;
        *(uint2*)(g_Mh + base + 1 * 512 + o) = *(uint2*)h1;
        *(uint2*)(g_Mh + base + 2 * 512 + o) = *(uint2*)h2;
    }
}

// ------------------------------- GEMM --------------------------------------
// compacted rows: out[orig[m], c] = tanh( sum_k M[m,k]*Bt[c,k] + bias[c] )
// CTA tile 128(M) x 256(N), 512 threads / 16 warps (4m x 4n), warp tile 32x64
// 4-stage cp.async; SINGLE-buffered frags (regs <= 128 at 512 thr, no spills)
#define TM 128
#define TN 256
#define TK 64
#define ROWB 144
#define MAT_A (128 * ROWB)
#define MAT_B (256 * ROWB)
#define STAGE_BYTES (MAT_A + MAT_B)
#define NSTAGE 4
#define GEMM_SMEM (NSTAGE * STAGE_BYTES)   // 221184

__global__ __launch_bounds__(512, 1)
void gemm_kernel(const float* __restrict__ bias, float* __restrict__ out) {
    const int Nc = g_Nc;
    const int mt = blockIdx.x >> 1;
    const int m0 = mt * TM;
    if (m0 >= Nc) return;            // compacted grid is data-dependent

    extern __shared__ char dsm[];
    const uint32_t sbase = smem_to_u32(dsm);

    const int tid  = threadIdx.x;
    const int lane = tid & 31;
    const int wid  = tid >> 5;
    const int wm   = wid & 3;          // 0..3 -> 32 rows each
    const int wn   = wid >> 2;         // 0..3 -> 64 cols each

    const int nt = blockIdx.x & 1;
    const int n0 = nt * TN;

    // ---- hoisted per-thread source pointers (2 A rows, 4 B rows) ----
    const char* aSrc[2];
    uint32_t    aOk[2];
    #pragma unroll
    for (int i = 0; i < 2; i++) {
        int idx = tid + i * 512;
        int row = idx >> 3;
        int ch  = idx & 7;
        int gr = m0 + row;
        aOk[i]  = (gr < Nc) ? 16u : 0u;
        aSrc[i] = (gr < Nc) ? (const char*)(g_Mh + (size_t)gr * K3) + ch * 16
                            : (const char*)g_Mh;
    }
    const char* bSrc[4];
    #pragma unroll
    for (int i = 0; i < 4; i++) {
        int idx = tid + i * 512;
        int row = idx >> 3;
        int ch  = idx & 7;
        int br = n0 + row;
        bSrc[i] = (const char*)(g_Bh + (size_t)br * K3) + ch * 16;
    }

    auto stage_off = [&](int s) { return sbase + (uint32_t)s * STAGE_BYTES; };

    auto load_stage = [&](int s, int kc) {
        uint32_t so = stage_off(s);
        int kbyte = kc * TK * 2;
        #pragma unroll
        for (int i = 0; i < 2; i++) {
            int idx = tid + i * 512;
            int row = idx >> 3;
            int ch  = idx & 7;
            uint32_t d = (uint32_t)(row * ROWB + ch * 16);
            cp_async16(so + d, aSrc[i] + kbyte, aOk[i]);
        }
        #pragma unroll
        for (int i = 0; i < 4; i++) {
            int idx = tid + i * 512;
            int row = idx >> 3;
            int ch  = idx & 7;
            uint32_t d = (uint32_t)(row * ROWB + ch * 16);
            cp_async16(so + MAT_A + d, bSrc[i] + kbyte, 16u);
        }
    };

    float acc[2][8][4];
    #pragma unroll
    for (int i = 0; i < 2; i++)
        #pragma unroll
        for (int j = 0; j < 8; j++)
            #pragma unroll
            for (int q = 0; q < 4; q++) acc[i][j][q] = 0.f;

    const uint32_t aRow = (uint32_t)(wm * 32 + (lane & 15));
    const uint32_t bRow = (uint32_t)(wn * 64 + (lane & 15));
    const uint32_t colB = (uint32_t)((lane >> 4) * 16);

    load_stage(0, 0);
    cp_commit();
    load_stage(1, 1);
    cp_commit();
    load_stage(2, 2);
    cp_commit();

    const int NKC = K3 / TK;   // 24
    int sidx = 0;
    for (int kc = 0; kc < NKC; kc++) {
        if (kc + 2 < NKC)      cp_wait2();
        else if (kc + 1 < NKC) cp_wait1();
        else                   cp_wait0();
        __syncthreads();
        if (kc + 3 < NKC) {
            int s3 = sidx + 3; if (s3 >= NSTAGE) s3 -= NSTAGE;
            load_stage(s3, kc + 3);
            cp_commit();
        }

        uint32_t so = stage_off(sidx);
        uint32_t aB   = so + aRow * ROWB + colB;
        uint32_t bHiB = so + MAT_A + bRow * ROWB + colB;

        #pragma unroll
        for (int k16 = 0; k16 < 4; k16++) {
            uint32_t kb = (uint32_t)(k16 * 32);
            uint32_t a[2][4], bh[4][4];
            #pragma unroll
            for (int i = 0; i < 2; i++)
                ldsm_x4(a[i], aB + (uint32_t)(i * 16) * ROWB + kb);
            #pragma unroll
            for (int g = 0; g < 4; g++)
                ldsm_x4(bh[g], bHiB + (uint32_t)(g * 16) * ROWB + kb);
            #pragma unroll
            for (int g = 0; g < 4; g++)
                #pragma unroll
                for (int i = 0; i < 2; i++) {
                    mma16816(acc[i][2*g],   a[i], bh[g][0], bh[g][2]);
                    mma16816(acc[i][2*g+1], a[i], bh[g][1], bh[g][3]);
                }
        }
        sidx++; if (sidx >= NSTAGE) sidx = 0;
    }

    // ---------------- epilogue: bias + tanh, scatter via g_orig ------------
    int orow[2][2];
    #pragma unroll
    for (int i = 0; i < 2; i++) {
        int r0 = m0 + wm * 32 + i * 16 + (lane >> 2);
        int r1 = r0 + 8;
        orow[i][0] = (r0 < Nc) ? __ldg(g_orig + r0) : -1;
        orow[i][1] = (r1 < Nc) ? __ldg(g_orig + r1) : -1;
    }
    #pragma unroll
    for (int j = 0; j < 8; j++) {
        int col = n0 + wn * 64 + j * 8 + (lane & 3) * 2;
        float b0 = __ldg(bias + col);
        float b1 = __ldg(bias + col + 1);
        #pragma unroll
        for (int i = 0; i < 2; i++) {
            if (orow[i][0] >= 0) {
                float2 o;
                o.x = tanh_fast(acc[i][j][0] + b0);
                o.y = tanh_fast(acc[i][j][1] + b1);
                *(float2*)(out + (size_t)orow[i][0] * C_DIM + col) = o;
            }
            if (orow[i][1] >= 0) {
                float2 o;
                o.x = tanh_fast(acc[i][j][2] + b0);
                o.y = tanh_fast(acc[i][j][3] + b1);
                *(float2*)(out + (size_t)orow[i][1] * C_DIM + col) = o;
            }
        }
    }
}

// ------------------------------ launch -------------------------------------
extern "C" void kernel_launch(void* const* d_in, const int* in_sizes, int n_in,
                              void* d_out, int out_size) {
    const float* x    = (const float*)d_in[0];
    const float* W    = (const float*)d_in[1];
    const float* bias = (const float*)d_in[2];
    const float* eta  = (const float*)d_in[3];
    const int*   src  = (const int*)d_in[4];
    const int*   dst  = (const int*)d_in[5];
    float* out = (float*)d_out;

    int N = in_sizes[0] / D_DIM;
    int E = in_sizes[4];

    cudaFuncSetAttribute(gemm_kernel,
                         cudaFuncAttributeMaxDynamicSharedMemorySize,
                         GEMM_SMEM);

    int maxEN = (E > N) ? E : N;
    int NB = (N + 511) / 512;          // scan blocks (<= NBMAX)

    // single stream, shortest serial chain
    histPrepW_kernel<<<PREPW_BLOCKS + (E + 255) / 256, 256>>>(W, dst, E);
    scan1_kernel<<<NB, 512>>>(N);
    scan3_kernel<<<NB, 512>>>(N, NB);
    fill_kernel<<<(maxEN + 255) / 256, 256>>>(dst, src, eta, E, N);
    reduce_kernel<<<(N * 64 + 255) / 256, 256>>>(x, bias, out, N);
    int mtiles = (N + TM - 1) / TM;    // worst-case grid; CTAs past g_Nc exit
    gemm_kernel<<<mtiles * 2, 512, GEMM_SMEM>>>(bias, out);
}